// round 6
// baseline (speedup 1.0000x reference)
#include <cuda_runtime.h>
#include <cuda_fp16.h>
#include <cstddef>

#define NN 100000
#define NE 3200000
#define NG 128
#define HD 64
#define BN_EPS 1e-5f
#define SCAN_BLK 1024
#define NBLK ((NN + SCAN_BLK - 1) / SCAN_BLK)

// ---------------- scratch (static device globals; no allocation) ----------------
__device__ __align__(16) int   g_count[NN];
__device__ __align__(16) int   g_rowptr[NN + 1];
__device__ __align__(16) int   g_cursor[NN];
__device__ __align__(16) int   g_bsum[NBLK];
__device__ __align__(16) int   g_flag[NBLK];
__device__ __align__(16) int   g_csr[NE];
__device__ __align__(16) float g_deg[NN];            // 1/max(deg,1)
__device__ __align__(16) float g_agg4[NN * 4];
__device__ __align__(16) float g_aggA[(size_t)NN * HD];
__device__ __align__(16) float g_hA[(size_t)NN * HD];   // layer1 pre-BN
__device__ __align__(16) float g_hB[(size_t)NN * HD];   // layer2 pre-BN
__device__ __align__(16) float g_hC[(size_t)NN * HD];   // layer3 pre-BN
__device__ __align__(16) __half g_h16A[(size_t)NN * HD]; // relu(bn1(hA)) fp16
__device__ __align__(16) __half g_h16B[(size_t)NN * HD]; // relu(bn2(hB)) fp16
__device__ __align__(16) __half g_h16C[(size_t)NN * HD]; // relu(bn3(hC)) fp16
__device__ __align__(16) float g_bnsum[3 * HD];
__device__ __align__(16) float g_bnsq[3 * HD];
__device__ __align__(16) float g_pool[NG * HD];
__device__ __align__(16) float g_cnt[NG];

// ---------------- helpers ----------------
__device__ __forceinline__ void red_add(float* p, float v) {
    asm volatile("red.global.add.f32 [%0], %1;" :: "l"(p), "f"(v) : "memory");
}
__device__ __forceinline__ void red_add_i(int* p, int v) {
    asm volatile("red.global.add.s32 [%0], %1;" :: "l"(p), "r"(v) : "memory");
}

// ---------------- zero the small scratch ----------------
__global__ void zero_small_kernel() {
    int i = blockIdx.x * blockDim.x + threadIdx.x;
    if (i < NN) g_count[i] = 0;
    if (i < NBLK) g_flag[i] = 0;
    if (i < NG * HD) g_pool[i] = 0.f;
    if (i < 3 * HD) { g_bnsum[i] = 0.f; g_bnsq[i] = 0.f; }
    if (i < NG) g_cnt[i] = 0.f;
}

// ---------------- CSR build: histogram (fire-and-forget reds) ----------------
__global__ void hist_kernel(const int* __restrict__ dst) {
    int e = blockIdx.x * blockDim.x + threadIdx.x;
    if (e < NE) red_add_i(&g_count[dst[e]], 1);
}

// ---------------- CSR build: single-kernel scan with decoupled lookback ----------------
// NBLK = 98 blocks <= 148 SMs -> all co-resident, lookback cannot deadlock.
__global__ void scan_kernel() {
    int bid = blockIdx.x;
    int i = bid * SCAN_BLK + threadIdx.x;
    int lane = threadIdx.x & 31, wid = threadIdx.x >> 5;
    int v = (i < NN) ? g_count[i] : 0;
    int inc = v;
#pragma unroll
    for (int o = 1; o < 32; o <<= 1) {
        int t = __shfl_up_sync(0xffffffffu, inc, o);
        if (lane >= o) inc += t;
    }
    __shared__ int wsum[32];
    __shared__ int blockOff;
    if (lane == 31) wsum[wid] = inc;
    __syncthreads();
    if (wid == 0) {
        int t = wsum[lane];
        int ti = t;
#pragma unroll
        for (int o = 1; o < 32; o <<= 1) {
            int u = __shfl_up_sync(0xffffffffu, ti, o);
            if (lane >= o) ti += u;
        }
        wsum[lane] = ti - t;   // exclusive warp offsets
    }
    __syncthreads();
    int excl = inc - v + wsum[wid];

    // publish block total
    if (threadIdx.x == SCAN_BLK - 1) {
        g_bsum[bid] = excl + v;
        __threadfence();
        atomicExch(&g_flag[bid], 1);
    }
    // lookback: accumulate predecessors
    if (threadIdx.x == 0) {
        int off = 0;
        for (int b = 0; b < bid; b++) {
            while (atomicAdd(&g_flag[b], 0) == 0) {}
            off += *((volatile int*)&g_bsum[b]);
        }
        blockOff = off;
    }
    __syncthreads();
    int rp = excl + blockOff;
    if (i < NN) {
        g_rowptr[i] = rp;
        g_cursor[i] = rp;
        g_deg[i] = 1.0f / fmaxf((float)v, 1.0f);
    }
    if (i == NN - 1) g_rowptr[NN] = NE;
}

// ---------------- CSR build: placement ----------------
__global__ void place_kernel(const int* __restrict__ src, const int* __restrict__ dst) {
    int e = blockIdx.x * blockDim.x + threadIdx.x;
    if (e >= NE) return;
    int pos = atomicAdd(&g_cursor[dst[e]], 1);
    g_csr[pos] = src[e];
}

// ---------------- layer-1 gather (4-dim): warp per node ----------------
__global__ void gather1_kernel(const float* __restrict__ x) {
    int wi = (blockIdx.x * blockDim.x + threadIdx.x) >> 5;
    if (wi >= NN) return;
    int lane = threadIdx.x & 31;
    int beg = g_rowptr[wi], end = g_rowptr[wi + 1];
    float4 acc = make_float4(0.f, 0.f, 0.f, 0.f);
    for (int i = beg + lane; i < end; i += 32) {
        int s = g_csr[i];
        float4 v = __ldg((const float4*)(x + 4 * (size_t)s));
        acc.x += v.x; acc.y += v.y; acc.z += v.z; acc.w += v.w;
    }
#pragma unroll
    for (int o = 16; o; o >>= 1) {
        acc.x += __shfl_xor_sync(0xffffffffu, acc.x, o);
        acc.y += __shfl_xor_sync(0xffffffffu, acc.y, o);
        acc.z += __shfl_xor_sync(0xffffffffu, acc.z, o);
        acc.w += __shfl_xor_sync(0xffffffffu, acc.w, o);
    }
    if (lane == 0) *(float4*)(g_agg4 + 4 * (size_t)wi) = acc;
}

// ---------------- layer-1 node transform + BN stats ----------------
__global__ void node1_kernel(const float* __restrict__ x, const float* __restrict__ wl,
                             const float* __restrict__ b, const float* __restrict__ wr) {
    __shared__ float wls[HD * 4], wrs[HD * 4], bs[HD];
    int tid = threadIdx.x;
    if (tid < HD * 4) { wls[tid] = wl[tid]; wrs[tid] = wr[tid]; }
    if (tid < HD) bs[tid] = b[tid];
    __syncthreads();

    int n = blockIdx.x * blockDim.x + tid;
    bool act = n < NN;
    float di = act ? g_deg[n] : 0.f;
    float4 a = act ? *(const float4*)(g_agg4 + 4 * (size_t)n) : make_float4(0, 0, 0, 0);
    a.x *= di; a.y *= di; a.z *= di; a.w *= di;
    float4 xv = act ? __ldg((const float4*)(x + 4 * (size_t)n)) : make_float4(0, 0, 0, 0);
    int lane = tid & 31;

#pragma unroll
    for (int fb = 0; fb < 16; fb++) {
        float o[4];
#pragma unroll
        for (int j = 0; j < 4; j++) {
            int f = fb * 4 + j;
            float acc = bs[f];
            acc = fmaf(a.x, wls[f * 4 + 0], acc);
            acc = fmaf(a.y, wls[f * 4 + 1], acc);
            acc = fmaf(a.z, wls[f * 4 + 2], acc);
            acc = fmaf(a.w, wls[f * 4 + 3], acc);
            acc = fmaf(xv.x, wrs[f * 4 + 0], acc);
            acc = fmaf(xv.y, wrs[f * 4 + 1], acc);
            acc = fmaf(xv.z, wrs[f * 4 + 2], acc);
            acc = fmaf(xv.w, wrs[f * 4 + 3], acc);
            o[j] = acc;
        }
        if (act) *(float4*)(g_hA + (size_t)n * HD + fb * 4) = make_float4(o[0], o[1], o[2], o[3]);
#pragma unroll
        for (int j = 0; j < 4; j++) {
            float h = act ? o[j] : 0.f;
            float s = h, q = h * h;
#pragma unroll
            for (int off = 16; off; off >>= 1) {
                s += __shfl_xor_sync(0xffffffffu, s, off);
                q += __shfl_xor_sync(0xffffffffu, q, off);
            }
            if (lane == 0) {
                red_add(&g_bnsum[fb * 4 + j], s);
                red_add(&g_bnsq[fb * 4 + j], q);
            }
        }
    }
}

// ---------------- convert: h_pre -> fp16 relu(bn(h)); BN finalize done in-block ----------------
// which: 0 -> hA->h16A, 1 -> hB->h16B, 2 -> hC->h16C. 256 threads/block.
__global__ void cvt_kernel(int which, const float* __restrict__ gamma,
                           const float* __restrict__ beta) {
    const float* __restrict__ hin = (which == 0) ? g_hA : (which == 1) ? g_hB : g_hC;
    __half* __restrict__ hout = (which == 0) ? g_h16A : (which == 1) ? g_h16B : g_h16C;
    __shared__ float sc_s[HD], sh_s[HD];
    int tid = threadIdx.x;
    if (tid < HD) {
        const float invn = 1.0f / (float)NN;
        float m = g_bnsum[which * HD + tid] * invn;
        float v = g_bnsq[which * HD + tid] * invn - m * m;
        float s = __ldg(gamma + tid) * rsqrtf(v + BN_EPS);
        sc_s[tid] = s;
        sh_s[tid] = __ldg(beta + tid) - m * s;
    }
    __syncthreads();
    int t = blockIdx.x * blockDim.x + tid;
    if (t >= NN * 8) return;
    int n = t >> 3, c = (t & 7) * 8;
    float4 v0 = __ldg((const float4*)(hin + (size_t)n * HD + c));
    float4 v1 = __ldg((const float4*)(hin + (size_t)n * HD + c + 4));
    float r0 = fmaxf(fmaf(v0.x, sc_s[c + 0], sh_s[c + 0]), 0.f);
    float r1 = fmaxf(fmaf(v0.y, sc_s[c + 1], sh_s[c + 1]), 0.f);
    float r2 = fmaxf(fmaf(v0.z, sc_s[c + 2], sh_s[c + 2]), 0.f);
    float r3 = fmaxf(fmaf(v0.w, sc_s[c + 3], sh_s[c + 3]), 0.f);
    float r4 = fmaxf(fmaf(v1.x, sc_s[c + 4], sh_s[c + 4]), 0.f);
    float r5 = fmaxf(fmaf(v1.y, sc_s[c + 5], sh_s[c + 5]), 0.f);
    float r6 = fmaxf(fmaf(v1.z, sc_s[c + 6], sh_s[c + 6]), 0.f);
    float r7 = fmaxf(fmaf(v1.w, sc_s[c + 7], sh_s[c + 7]), 0.f);
    __half2* dst = (__half2*)(hout + (size_t)n * HD + c);
    dst[0] = __floats2half2_rn(r0, r1);
    dst[1] = __floats2half2_rn(r2, r3);
    dst[2] = __floats2half2_rn(r4, r5);
    dst[3] = __floats2half2_rn(r6, r7);
}

// ---------------- 64-wide gather over fp16: 2 nodes per warp, LDG.64 per lane ----------------
// Half-warp per node: lane hl of each half owns cols 4hl..4hl+3 (one uint2 = 8B).
// One shuffle + one LDG.64 instruction serves 2 edges (one per half).
__global__ void gather64_kernel(int which) {
    const __half2* __restrict__ hin = (const __half2*)((which == 0) ? g_h16A : g_h16B);
    int warp = (blockIdx.x * blockDim.x + threadIdx.x) >> 5;
    if (warp >= NN / 2) return;
    int lane = threadIdx.x & 31;
    int half = lane >> 4;
    int hl = lane & 15;
    int node = warp * 2 + half;
    int beg = g_rowptr[node], end = g_rowptr[node + 1];
    int cnt = end - beg;
    int ocnt = __shfl_xor_sync(0xffffffffu, cnt, 16);
    int maxcnt = (cnt > ocnt) ? cnt : ocnt;   // uniform across warp
    int srcbase = half << 4;
    float a0 = 0.f, a1 = 0.f, a2 = 0.f, a3 = 0.f;
    for (int done = 0; done < maxcnt; done += 16) {
        int idx = beg + done + hl;
        int sv = (idx < end) ? __ldg(g_csr + idx) : 0;
        int m = cnt - done;             // may be <=0 for the shorter half
        int mmax = maxcnt - done; if (mmax > 16) mmax = 16;
#pragma unroll 4
        for (int j = 0; j < mmax; j++) {
            int s = __shfl_sync(0xffffffffu, sv, srcbase + j);
            uint2 p = __ldg((const uint2*)(hin + (size_t)s * 32 + 2 * hl));
            if (j < m) {
                float2 u = __half22float2(*reinterpret_cast<__half2*>(&p.x));
                float2 w = __half22float2(*reinterpret_cast<__half2*>(&p.y));
                a0 += u.x; a1 += u.y; a2 += w.x; a3 += w.y;
            }
        }
    }
    *(float4*)(g_aggA + (size_t)node * HD + 4 * hl) = make_float4(a0, a1, a2, a3);
}

// ---------------- layer 2/3 node transform (smem GEMM) + BN stats ----------------
// 128 threads, 64 nodes/block. Phase 0: (Wl, agg*deg_inv); phase 1: (Wr, h16 prev).
// which: 0 -> in h16A, out hB, stat 1;  1 -> in h16B, out hC, stat 2.
__global__ void node64_kernel(int which, const float* __restrict__ wl,
                              const float* __restrict__ bias, const float* __restrict__ wr) {
    const __half2* __restrict__ h16in = (const __half2*)((which == 0) ? g_h16A : g_h16B);
    float* __restrict__ hout = (which == 0) ? g_hB : g_hC;
    int stat = which + 1;

    __shared__ __align__(16) float in_s[64 * 69];
    __shared__ __align__(16) float W_s[64 * 68];

    int tid = threadIdx.x;
    int base = blockIdx.x * 64;
    int tx = tid & 7, ty = tid >> 3;
    int f0 = tx * 8, n0 = ty * 4;

    float acc[4][8];
#pragma unroll
    for (int i = 0; i < 4; i++)
#pragma unroll
        for (int j = 0; j < 8; j++) acc[i][j] = 0.f;

    for (int phase = 0; phase < 2; phase++) {
        const float* __restrict__ W = phase ? wr : wl;
        for (int i = tid; i < 64 * 16; i += 128) {
            int f = i >> 4, kc = (i & 15) * 4;
            float4 a = __ldg((const float4*)(W + f * 64 + kc));
            W_s[(kc + 0) * 68 + f] = a.x;
            W_s[(kc + 1) * 68 + f] = a.y;
            W_s[(kc + 2) * 68 + f] = a.z;
            W_s[(kc + 3) * 68 + f] = a.w;
        }
        if (phase == 0) {
            for (int i = tid; i < 64 * 16; i += 128) {
                int n = i >> 4, kc = (i & 15) * 4;
                int gn = base + n;
                float4 v = make_float4(0, 0, 0, 0);
                if (gn < NN) {
                    float di = g_deg[gn];
                    v = __ldg((const float4*)(g_aggA + (size_t)gn * HD + kc));
                    v.x *= di; v.y *= di; v.z *= di; v.w *= di;
                }
                in_s[n * 69 + kc + 0] = v.x;
                in_s[n * 69 + kc + 1] = v.y;
                in_s[n * 69 + kc + 2] = v.z;
                in_s[n * 69 + kc + 3] = v.w;
            }
        } else {
            for (int i = tid; i < 64 * 16; i += 128) {
                int n = i >> 4, cp = (i & 15) * 2;   // half2 pair index
                int gn = base + n;
                float2 f0v = make_float2(0.f, 0.f), f1v = make_float2(0.f, 0.f);
                if (gn < NN) {
                    f0v = __half22float2(__ldg(h16in + (size_t)gn * 32 + cp));
                    f1v = __half22float2(__ldg(h16in + (size_t)gn * 32 + cp + 1));
                }
                in_s[n * 69 + 2 * cp + 0] = f0v.x;
                in_s[n * 69 + 2 * cp + 1] = f0v.y;
                in_s[n * 69 + 2 * cp + 2] = f1v.x;
                in_s[n * 69 + 2 * cp + 3] = f1v.y;
            }
        }
        __syncthreads();
#pragma unroll 8
        for (int k = 0; k < 64; k++) {
            float4 w0 = *(const float4*)&W_s[k * 68 + f0];
            float4 w1 = *(const float4*)&W_s[k * 68 + f0 + 4];
#pragma unroll
            for (int i = 0; i < 4; i++) {
                float a = in_s[(n0 + i) * 69 + k];
                acc[i][0] = fmaf(a, w0.x, acc[i][0]);
                acc[i][1] = fmaf(a, w0.y, acc[i][1]);
                acc[i][2] = fmaf(a, w0.z, acc[i][2]);
                acc[i][3] = fmaf(a, w0.w, acc[i][3]);
                acc[i][4] = fmaf(a, w1.x, acc[i][4]);
                acc[i][5] = fmaf(a, w1.y, acc[i][5]);
                acc[i][6] = fmaf(a, w1.z, acc[i][6]);
                acc[i][7] = fmaf(a, w1.w, acc[i][7]);
            }
        }
        __syncthreads();
    }

    // epilogue: bias, store, BN partial sums
    float bsv[8];
#pragma unroll
    for (int j = 0; j < 8; j++) bsv[j] = __ldg(bias + f0 + j);

    float psum[8], psq[8];
#pragma unroll
    for (int j = 0; j < 8; j++) { psum[j] = 0.f; psq[j] = 0.f; }

#pragma unroll
    for (int i = 0; i < 4; i++) {
        int gn = base + n0 + i;
        if (gn < NN) {
            float h[8];
#pragma unroll
            for (int j = 0; j < 8; j++) {
                h[j] = acc[i][j] + bsv[j];
                psum[j] += h[j];
                psq[j] += h[j] * h[j];
            }
            *(float4*)(hout + (size_t)gn * HD + f0) = make_float4(h[0], h[1], h[2], h[3]);
            *(float4*)(hout + (size_t)gn * HD + f0 + 4) = make_float4(h[4], h[5], h[6], h[7]);
        }
    }
#pragma unroll
    for (int j = 0; j < 8; j++) {
        float s = psum[j], q = psq[j];
        s += __shfl_xor_sync(0xffffffffu, s, 8);
        q += __shfl_xor_sync(0xffffffffu, q, 8);
        s += __shfl_xor_sync(0xffffffffu, s, 16);
        q += __shfl_xor_sync(0xffffffffu, q, 16);
        if (((tid & 31) >> 3) == 0) {
            red_add(&g_bnsum[stat * HD + f0 + j], s);
            red_add(&g_bnsq[stat * HD + f0 + j], q);
        }
    }
}

// ---------------- mean-pool over graphs (sorted batch -> run-flush) ----------------
__global__ void pool_kernel(const int* __restrict__ batch) {
    const __half2* __restrict__ h16 = (const __half2*)g_h16C;
    int warp = (blockIdx.x * blockDim.x + threadIdx.x) >> 5;
    const int nwarps = NN / 32;  // 3125
    if (warp >= nwarps) return;
    int lane = threadIdx.x & 31;
    int n0 = warp * 32, n1 = n0 + 32;
    int cur = __ldg(batch + n0);
    int runStart = n0;
    float a0 = 0.f, a1 = 0.f;
    for (int n = n0; n < n1; n++) {
        int b = __ldg(batch + n);
        if (b != cur) {
            red_add(&g_pool[cur * HD + 2 * lane], a0);
            red_add(&g_pool[cur * HD + 2 * lane + 1], a1);
            if (lane == 0) red_add(&g_cnt[cur], (float)(n - runStart));
            cur = b; runStart = n; a0 = 0.f; a1 = 0.f;
        }
        float2 f = __half22float2(__ldg(h16 + (size_t)n * 32 + lane));
        a0 += f.x; a1 += f.y;
    }
    red_add(&g_pool[cur * HD + 2 * lane], a0);
    red_add(&g_pool[cur * HD + 2 * lane + 1], a1);
    if (lane == 0) red_add(&g_cnt[cur], (float)(n1 - runStart));
}

// ---------------- MLP head ----------------
__global__ void head_kernel(const float* __restrict__ fc1w, const float* __restrict__ fc1b,
                            const float* __restrict__ fc2w, const float* __restrict__ fc2b,
                            float* __restrict__ out) {
    __shared__ float w1s[64 * 64];
    int tid = threadIdx.x;  // 128
    for (int i = tid; i < 64 * 64; i += 128) w1s[i] = fc1w[i];
    __syncthreads();
    if (tid < NG) {
        float ci = 1.0f / fmaxf(g_cnt[tid], 1.0f);
        float p[64];
#pragma unroll
        for (int f = 0; f < 64; f++) p[f] = g_pool[tid * HD + f] * ci;
        float hid[64];
#pragma unroll
        for (int j = 0; j < 64; j++) {
            float acc = fc1b[j];
#pragma unroll
            for (int f = 0; f < 64; f++) acc = fmaf(p[f], w1s[j * 64 + f], acc);
            hid[j] = fmaxf(acc, 0.f);
        }
#pragma unroll
        for (int u = 0; u < 2; u++) {
            float acc = fc2b[u];
#pragma unroll
            for (int j = 0; j < 64; j++) acc = fmaf(hid[j], __ldg(fc2w + u * 64 + j), acc);
            out[tid * 2 + u] = acc;
        }
    }
}

// ---------------- launch ----------------
extern "C" void kernel_launch(void* const* d_in, const int* in_sizes, int n_in,
                              void* d_out, int out_size) {
    const float* x    = (const float*)d_in[0];
    const int*   ei   = (const int*)d_in[1];
    const int*   src  = ei;
    const int*   dst  = ei + NE;
    const int*   bat  = (const int*)d_in[2];
    const float* w1l  = (const float*)d_in[3];
    const float* b1   = (const float*)d_in[4];
    const float* w1r  = (const float*)d_in[5];
    const float* g1   = (const float*)d_in[6];
    const float* be1  = (const float*)d_in[7];
    const float* w2l  = (const float*)d_in[8];
    const float* b2   = (const float*)d_in[9];
    const float* w2r  = (const float*)d_in[10];
    const float* g2   = (const float*)d_in[11];
    const float* be2  = (const float*)d_in[12];
    const float* w3l  = (const float*)d_in[13];
    const float* b3   = (const float*)d_in[14];
    const float* w3r  = (const float*)d_in[15];
    const float* g3   = (const float*)d_in[16];
    const float* be3  = (const float*)d_in[17];
    const float* fc1w = (const float*)d_in[18];
    const float* fc1b = (const float*)d_in[19];
    const float* fc2w = (const float*)d_in[20];
    const float* fc2b = (const float*)d_in[21];
    float* out = (float*)d_out;

    // CSR build (place_kernel is launch #4 -> gets profiled)
    zero_small_kernel<<<(NN + 255) / 256, 256>>>();
    hist_kernel<<<(NE + 255) / 256, 256>>>(dst);
    scan_kernel<<<NBLK, SCAN_BLK>>>();
    place_kernel<<<(NE + 255) / 256, 256>>>(src, dst);

    // layer 1
    gather1_kernel<<<(NN * 32 + 255) / 256, 256>>>(x);
    node1_kernel<<<(NN + 255) / 256, 256>>>(x, w1l, b1, w1r);
    cvt_kernel<<<(NN * 8 + 255) / 256, 256>>>(0, g1, be1);

    // layer 2
    gather64_kernel<<<(NN / 2 * 32 + 255) / 256, 256>>>(0);
    node64_kernel<<<(NN + 63) / 64, 128>>>(0, w2l, b2, w2r);
    cvt_kernel<<<(NN * 8 + 255) / 256, 256>>>(1, g2, be2);

    // layer 3
    gather64_kernel<<<(NN / 2 * 32 + 255) / 256, 256>>>(1);
    node64_kernel<<<(NN + 63) / 64, 128>>>(1, w3l, b3, w3r);
    cvt_kernel<<<(NN * 8 + 255) / 256, 256>>>(2, g3, be3);

    // pool + head
    pool_kernel<<<(NN + 255) / 256, 256>>>(bat);
    head_kernel<<<1, 128>>>(fc1w, fc1b, fc2w, fc2b, out);
}

// round 9
// speedup vs baseline: 1.7296x; 1.7296x over previous
#include <cuda_runtime.h>
#include <cuda_fp16.h>
#include <cstddef>
#include <cstdint>

#define NN 100000
#define NE 3200000
#define NG 128
#define HD 64
#define BN_EPS 1e-5f
#define SCAN_BLK 1024
#define NBLK ((NN + SCAN_BLK - 1) / SCAN_BLK)

// ---------------- scratch (static device globals; no allocation) ----------------
__device__ __align__(16) int   g_count[NN];
__device__ __align__(16) int   g_rowptr[NN + 1];
__device__ __align__(16) int   g_cursor[NN];
__device__ __align__(16) int   g_bsum[NBLK];
__device__ __align__(16) int   g_flag[NBLK];
__device__ __align__(16) int   g_csr[NE];
__device__ __align__(16) float g_deg[NN];            // 1/max(deg,1)
__device__ __align__(16) float g_agg4[NN * 4];
__device__ __align__(16) float g_aggA[(size_t)NN * HD];
__device__ __align__(16) float g_hA[(size_t)NN * HD];   // layer1 pre-BN
__device__ __align__(16) float g_hB[(size_t)NN * HD];   // layer2 pre-BN
__device__ __align__(16) float g_hC[(size_t)NN * HD];   // layer3 pre-BN
__device__ __align__(16) __half g_h16A[(size_t)NN * HD]; // relu(bn1(hA)) fp16
__device__ __align__(16) __half g_h16B[(size_t)NN * HD]; // relu(bn2(hB)) fp16
__device__ __align__(16) __half g_h16C[(size_t)NN * HD]; // relu(bn3(hC)) fp16
__device__ __align__(16) float g_bnsum[3 * HD];
__device__ __align__(16) float g_bnsq[3 * HD];
__device__ __align__(16) float g_pool[NG * HD];
__device__ __align__(16) float g_cnt[NG];

// ---------------- helpers ----------------
__device__ __forceinline__ void red_add(float* p, float v) {
    asm volatile("red.global.add.f32 [%0], %1;" :: "l"(p), "f"(v) : "memory");
}
__device__ __forceinline__ void red_add_i(int* p, int v) {
    asm volatile("red.global.add.s32 [%0], %1;" :: "l"(p), "r"(v) : "memory");
}

// ---------------- zero the small scratch ----------------
__global__ void zero_small_kernel() {
    int i = blockIdx.x * blockDim.x + threadIdx.x;
    if (i < NN) g_count[i] = 0;
    if (i < NBLK) g_flag[i] = 0;
    if (i < NG * HD) g_pool[i] = 0.f;
    if (i < 3 * HD) { g_bnsum[i] = 0.f; g_bnsq[i] = 0.f; }
    if (i < NG) g_cnt[i] = 0.f;
}

// ---------------- CSR build: histogram (fire-and-forget reds) ----------------
__global__ void hist_kernel(const int* __restrict__ dst) {
    int e = blockIdx.x * blockDim.x + threadIdx.x;
    if (e < NE) red_add_i(&g_count[dst[e]], 1);
}

// ---------------- CSR build: single-kernel scan, parallel lookback ----------------
// NBLK = 98 blocks <= 148 SMs -> all co-resident, lookback cannot deadlock.
__global__ void scan_kernel() {
    int bid = blockIdx.x;
    int i = bid * SCAN_BLK + threadIdx.x;
    int lane = threadIdx.x & 31, wid = threadIdx.x >> 5;
    int v = (i < NN) ? g_count[i] : 0;
    int inc = v;
#pragma unroll
    for (int o = 1; o < 32; o <<= 1) {
        int t = __shfl_up_sync(0xffffffffu, inc, o);
        if (lane >= o) inc += t;
    }
    __shared__ int wsum[32];
    __shared__ int blockOff;
    if (lane == 31) wsum[wid] = inc;
    __syncthreads();
    if (wid == 0) {
        int t = wsum[lane];
        int ti = t;
#pragma unroll
        for (int o = 1; o < 32; o <<= 1) {
            int u = __shfl_up_sync(0xffffffffu, ti, o);
            if (lane >= o) ti += u;
        }
        wsum[lane] = ti - t;   // exclusive warp offsets
    }
    __syncthreads();
    int excl = inc - v + wsum[wid];

    // publish block total
    if (threadIdx.x == SCAN_BLK - 1) {
        g_bsum[bid] = excl + v;
        __threadfence();
        atomicExch(&g_flag[bid], 1);
    }
    // parallel lookback: 32 lanes poll predecessors concurrently
    if (wid == 0) {
        int off = 0;
        for (int b = lane; b < bid; b += 32) {
            while (atomicAdd(&g_flag[b], 0) == 0) {}
            off += *((volatile int*)&g_bsum[b]);
        }
#pragma unroll
        for (int o = 16; o; o >>= 1) off += __shfl_xor_sync(0xffffffffu, off, o);
        if (lane == 0) blockOff = off;
    }
    __syncthreads();
    int rp = excl + blockOff;
    if (i < NN) {
        g_rowptr[i] = rp;
        g_cursor[i] = rp;
        g_deg[i] = 1.0f / fmaxf((float)v, 1.0f);
    }
    if (i == NN - 1) g_rowptr[NN] = NE;
}

// ---------------- CSR build: placement ----------------
__global__ void place_kernel(const int* __restrict__ src, const int* __restrict__ dst) {
    int e = blockIdx.x * blockDim.x + threadIdx.x;
    if (e >= NE) return;
    int pos = atomicAdd(&g_cursor[dst[e]], 1);
    g_csr[pos] = src[e];
}

// ---------------- layer-1 gather (4-dim): warp per node ----------------
__global__ void gather1_kernel(const float* __restrict__ x) {
    int wi = (blockIdx.x * blockDim.x + threadIdx.x) >> 5;
    if (wi >= NN) return;
    int lane = threadIdx.x & 31;
    int beg = g_rowptr[wi], end = g_rowptr[wi + 1];
    float4 acc = make_float4(0.f, 0.f, 0.f, 0.f);
    for (int i = beg + lane; i < end; i += 32) {
        int s = g_csr[i];
        float4 v = __ldg((const float4*)(x + 4 * (size_t)s));
        acc.x += v.x; acc.y += v.y; acc.z += v.z; acc.w += v.w;
    }
#pragma unroll
    for (int o = 16; o; o >>= 1) {
        acc.x += __shfl_xor_sync(0xffffffffu, acc.x, o);
        acc.y += __shfl_xor_sync(0xffffffffu, acc.y, o);
        acc.z += __shfl_xor_sync(0xffffffffu, acc.z, o);
        acc.w += __shfl_xor_sync(0xffffffffu, acc.w, o);
    }
    if (lane == 0) *(float4*)(g_agg4 + 4 * (size_t)wi) = acc;
}

// ---------------- layer-1 node transform + BN stats ----------------
__global__ void node1_kernel(const float* __restrict__ x, const float* __restrict__ wl,
                             const float* __restrict__ b, const float* __restrict__ wr) {
    __shared__ float wls[HD * 4], wrs[HD * 4], bs[HD];
    int tid = threadIdx.x;
    if (tid < HD * 4) { wls[tid] = wl[tid]; wrs[tid] = wr[tid]; }
    if (tid < HD) bs[tid] = b[tid];
    __syncthreads();

    int n = blockIdx.x * blockDim.x + tid;
    bool act = n < NN;
    float di = act ? g_deg[n] : 0.f;
    float4 a = act ? *(const float4*)(g_agg4 + 4 * (size_t)n) : make_float4(0, 0, 0, 0);
    a.x *= di; a.y *= di; a.z *= di; a.w *= di;
    float4 xv = act ? __ldg((const float4*)(x + 4 * (size_t)n)) : make_float4(0, 0, 0, 0);
    int lane = tid & 31;

#pragma unroll
    for (int fb = 0; fb < 16; fb++) {
        float o[4];
#pragma unroll
        for (int j = 0; j < 4; j++) {
            int f = fb * 4 + j;
            float acc = bs[f];
            acc = fmaf(a.x, wls[f * 4 + 0], acc);
            acc = fmaf(a.y, wls[f * 4 + 1], acc);
            acc = fmaf(a.z, wls[f * 4 + 2], acc);
            acc = fmaf(a.w, wls[f * 4 + 3], acc);
            acc = fmaf(xv.x, wrs[f * 4 + 0], acc);
            acc = fmaf(xv.y, wrs[f * 4 + 1], acc);
            acc = fmaf(xv.z, wrs[f * 4 + 2], acc);
            acc = fmaf(xv.w, wrs[f * 4 + 3], acc);
            o[j] = acc;
        }
        if (act) *(float4*)(g_hA + (size_t)n * HD + fb * 4) = make_float4(o[0], o[1], o[2], o[3]);
#pragma unroll
        for (int j = 0; j < 4; j++) {
            float h = act ? o[j] : 0.f;
            float s = h, q = h * h;
#pragma unroll
            for (int off = 16; off; off >>= 1) {
                s += __shfl_xor_sync(0xffffffffu, s, off);
                q += __shfl_xor_sync(0xffffffffu, q, off);
            }
            if (lane == 0) {
                red_add(&g_bnsum[fb * 4 + j], s);
                red_add(&g_bnsq[fb * 4 + j], q);
            }
        }
    }
}

// ---------------- convert: h_pre -> fp16 relu(bn(h)); BN finalize done in-block ----------------
__global__ void cvt_kernel(int which, const float* __restrict__ gamma,
                           const float* __restrict__ beta) {
    const float* __restrict__ hin = (which == 0) ? g_hA : (which == 1) ? g_hB : g_hC;
    __half* __restrict__ hout = (which == 0) ? g_h16A : (which == 1) ? g_h16B : g_h16C;
    __shared__ float sc_s[HD], sh_s[HD];
    int tid = threadIdx.x;
    if (tid < HD) {
        const float invn = 1.0f / (float)NN;
        float m = g_bnsum[which * HD + tid] * invn;
        float v = g_bnsq[which * HD + tid] * invn - m * m;
        float s = __ldg(gamma + tid) * rsqrtf(v + BN_EPS);
        sc_s[tid] = s;
        sh_s[tid] = __ldg(beta + tid) - m * s;
    }
    __syncthreads();
    int t = blockIdx.x * blockDim.x + tid;
    if (t >= NN * 8) return;
    int n = t >> 3, c = (t & 7) * 8;
    float4 v0 = __ldg((const float4*)(hin + (size_t)n * HD + c));
    float4 v1 = __ldg((const float4*)(hin + (size_t)n * HD + c + 4));
    float r0 = fmaxf(fmaf(v0.x, sc_s[c + 0], sh_s[c + 0]), 0.f);
    float r1 = fmaxf(fmaf(v0.y, sc_s[c + 1], sh_s[c + 1]), 0.f);
    float r2 = fmaxf(fmaf(v0.z, sc_s[c + 2], sh_s[c + 2]), 0.f);
    float r3 = fmaxf(fmaf(v0.w, sc_s[c + 3], sh_s[c + 3]), 0.f);
    float r4 = fmaxf(fmaf(v1.x, sc_s[c + 4], sh_s[c + 4]), 0.f);
    float r5 = fmaxf(fmaf(v1.y, sc_s[c + 5], sh_s[c + 5]), 0.f);
    float r6 = fmaxf(fmaf(v1.z, sc_s[c + 6], sh_s[c + 6]), 0.f);
    float r7 = fmaxf(fmaf(v1.w, sc_s[c + 7], sh_s[c + 7]), 0.f);
    __half2* dst = (__half2*)(hout + (size_t)n * HD + c);
    dst[0] = __floats2half2_rn(r0, r1);
    dst[1] = __floats2half2_rn(r2, r3);
    dst[2] = __floats2half2_rn(r4, r5);
    dst[3] = __floats2half2_rn(r6, r7);
}

// ---------------- 64-wide gather over fp16 features (warp/node) ----------------
__global__ void gather64_kernel(int which) {
    const __half2* __restrict__ hin = (const __half2*)((which == 0) ? g_h16A : g_h16B);
    int wi = (blockIdx.x * blockDim.x + threadIdx.x) >> 5;
    if (wi >= NN) return;
    int lane = threadIdx.x & 31;
    int beg = g_rowptr[wi], end = g_rowptr[wi + 1];
    float a0 = 0.f, a1 = 0.f;
    for (int base = beg; base < end; base += 32) {
        int idx = base + lane;
        int sv = (idx < end) ? g_csr[idx] : 0;
        int m = end - base;
        if (m > 32) m = 32;
        int j = 0;
        for (; j + 4 <= m; j += 4) {
            int s0 = __shfl_sync(0xffffffffu, sv, j + 0);
            int s1 = __shfl_sync(0xffffffffu, sv, j + 1);
            int s2 = __shfl_sync(0xffffffffu, sv, j + 2);
            int s3 = __shfl_sync(0xffffffffu, sv, j + 3);
            __half2 v0 = __ldg(hin + (size_t)s0 * 32 + lane);
            __half2 v1 = __ldg(hin + (size_t)s1 * 32 + lane);
            __half2 v2 = __ldg(hin + (size_t)s2 * 32 + lane);
            __half2 v3 = __ldg(hin + (size_t)s3 * 32 + lane);
            float2 f0 = __half22float2(v0);
            float2 f1 = __half22float2(v1);
            float2 f2 = __half22float2(v2);
            float2 f3 = __half22float2(v3);
            a0 += f0.x + f1.x; a1 += f0.y + f1.y;
            a0 += f2.x + f3.x; a1 += f2.y + f3.y;
        }
        for (; j < m; j++) {
            int s = __shfl_sync(0xffffffffu, sv, j);
            float2 f = __half22float2(__ldg(hin + (size_t)s * 32 + lane));
            a0 += f.x; a1 += f.y;
        }
    }
    *(float2*)(g_aggA + (size_t)wi * HD + 2 * lane) = make_float2(a0, a1);
}

// ---------------- layer 2/3 node transform: tensor-core GEMM + BN stats ----------------
// 128 threads (4 warps), 64 nodes/block. One fused K=128 GEMM:
//   h = [deg_inv*agg | h16_prev] (64x128 fp16)  @  [Wl | Wr]^T (128x64 fp16), fp32 accum.
// Warp w computes rows 16w..16w+15 via mma.sync.m16n8k16; 8 n-tiles x 8 k-steps.
__global__ void node64_kernel(int which, const float* __restrict__ wl,
                              const float* __restrict__ bias, const float* __restrict__ wr) {
    const __half* __restrict__ h16in = (which == 0) ? g_h16A : g_h16B;
    float* __restrict__ hout = (which == 0) ? g_hB : g_hC;
    int stat = which + 1;

    __shared__ __align__(16) __half in_s[64 * 136];   // 64 rows x (128 + 8 pad)
    __shared__ __align__(16) __half w_s[64 * 136];    // 64 f-rows x (128 + 8 pad)

    int tid = threadIdx.x;
    int base = blockIdx.x * 64;

    // fill weights: w_s[f][k] = Wcat[f][k]  (k<64: wl, else wr)
    for (int i = tid; i < 64 * 16; i += 128) {
        int f = i >> 4, c8 = (i & 15) * 8;
        const float* sp = (c8 < 64) ? (wl + f * 64 + c8) : (wr + f * 64 + (c8 - 64));
        float4 u = __ldg((const float4*)sp);
        float4 v = __ldg((const float4*)(sp + 4));
        __half2* dst = (__half2*)(w_s + f * 136 + c8);
        dst[0] = __floats2half2_rn(u.x, u.y);
        dst[1] = __floats2half2_rn(u.z, u.w);
        dst[2] = __floats2half2_rn(v.x, v.y);
        dst[3] = __floats2half2_rn(v.z, v.w);
    }
    // fill inputs: cols 0-63 = deg_inv*agg (fp32->fp16), 64-127 = h16 prev (copy)
    for (int i = tid; i < 64 * 16; i += 128) {
        int n = i >> 4, c8 = (i & 15) * 8;
        int gn = base + n;
        __half2 h0, h1, h2, h3;
        if (gn < NN) {
            if (c8 < 64) {
                float di = g_deg[gn];
                float4 u = __ldg((const float4*)(g_aggA + (size_t)gn * HD + c8));
                float4 v = __ldg((const float4*)(g_aggA + (size_t)gn * HD + c8 + 4));
                h0 = __floats2half2_rn(u.x * di, u.y * di);
                h1 = __floats2half2_rn(u.z * di, u.w * di);
                h2 = __floats2half2_rn(v.x * di, v.y * di);
                h3 = __floats2half2_rn(v.z * di, v.w * di);
            } else {
                const __half2* sp = (const __half2*)(h16in + (size_t)gn * HD + (c8 - 64));
                h0 = sp[0]; h1 = sp[1]; h2 = sp[2]; h3 = sp[3];
            }
        } else {
            h0 = h1 = h2 = h3 = __floats2half2_rn(0.f, 0.f);
        }
        __half2* dst = (__half2*)(in_s + n * 136 + c8);
        dst[0] = h0; dst[1] = h1; dst[2] = h2; dst[3] = h3;
    }
    __syncthreads();

    int lane = tid & 31, w = tid >> 5;
    int g = lane >> 2, iq = lane & 3;
    int row0 = 16 * w + g;            // local row for c0/c1 (row0+8 for c2/c3)

    float c[8][4];
#pragma unroll
    for (int nt = 0; nt < 8; nt++)
#pragma unroll
        for (int r = 0; r < 4; r++) c[nt][r] = 0.f;

    const __half* As  = in_s + row0 * 136;
    const __half* As8 = in_s + (row0 + 8) * 136;
#pragma unroll
    for (int kt = 0; kt < 8; kt++) {
        int k0 = kt * 16 + 2 * iq;
        uint32_t a0 = *(const uint32_t*)(As  + k0);
        uint32_t a1 = *(const uint32_t*)(As8 + k0);
        uint32_t a2 = *(const uint32_t*)(As  + k0 + 8);
        uint32_t a3 = *(const uint32_t*)(As8 + k0 + 8);
#pragma unroll
        for (int nt = 0; nt < 8; nt++) {
            const __half* Bs = w_s + (nt * 8 + g) * 136;
            uint32_t b0 = *(const uint32_t*)(Bs + k0);
            uint32_t b1 = *(const uint32_t*)(Bs + k0 + 8);
            asm volatile(
                "mma.sync.aligned.m16n8k16.row.col.f32.f16.f16.f32 "
                "{%0,%1,%2,%3}, {%4,%5,%6,%7}, {%8,%9}, {%0,%1,%2,%3};"
                : "+f"(c[nt][0]), "+f"(c[nt][1]), "+f"(c[nt][2]), "+f"(c[nt][3])
                : "r"(a0), "r"(a1), "r"(a2), "r"(a3), "r"(b0), "r"(b1));
        }
    }

    // epilogue: bias add, store pre-BN h, BN stats
    int gn0 = base + row0;
    int gn8 = gn0 + 8;
    bool v0 = gn0 < NN, v8 = gn8 < NN;
#pragma unroll
    for (int nt = 0; nt < 8; nt++) {
        int col = nt * 8 + 2 * iq;
        float b0v = __ldg(bias + col), b1v = __ldg(bias + col + 1);
        float h0 = c[nt][0] + b0v, h1 = c[nt][1] + b1v;
        float h2 = c[nt][2] + b0v, h3 = c[nt][3] + b1v;
        if (v0) *(float2*)(hout + (size_t)gn0 * HD + col) = make_float2(h0, h1);
        if (v8) *(float2*)(hout + (size_t)gn8 * HD + col) = make_float2(h2, h3);
        float ps0 = (v0 ? h0 : 0.f) + (v8 ? h2 : 0.f);
        float ps1 = (v0 ? h1 : 0.f) + (v8 ? h3 : 0.f);
        float qs0 = (v0 ? h0 * h0 : 0.f) + (v8 ? h2 * h2 : 0.f);
        float qs1 = (v0 ? h1 * h1 : 0.f) + (v8 ? h3 * h3 : 0.f);
#pragma unroll
        for (int o = 4; o < 32; o <<= 1) {
            ps0 += __shfl_xor_sync(0xffffffffu, ps0, o);
            ps1 += __shfl_xor_sync(0xffffffffu, ps1, o);
            qs0 += __shfl_xor_sync(0xffffffffu, qs0, o);
            qs1 += __shfl_xor_sync(0xffffffffu, qs1, o);
        }
        if (g == 0) {
            red_add(&g_bnsum[stat * HD + col],     ps0);
            red_add(&g_bnsum[stat * HD + col + 1], ps1);
            red_add(&g_bnsq[stat * HD + col],      qs0);
            red_add(&g_bnsq[stat * HD + col + 1],  qs1);
        }
    }
}

// ---------------- mean-pool over graphs (sorted batch -> run-flush) ----------------
__global__ void pool_kernel(const int* __restrict__ batch) {
    const __half2* __restrict__ h16 = (const __half2*)g_h16C;
    int warp = (blockIdx.x * blockDim.x + threadIdx.x) >> 5;
    const int nwarps = NN / 32;  // 3125
    if (warp >= nwarps) return;
    int lane = threadIdx.x & 31;
    int n0 = warp * 32, n1 = n0 + 32;
    int cur = __ldg(batch + n0);
    int runStart = n0;
    float a0 = 0.f, a1 = 0.f;
    for (int n = n0; n < n1; n++) {
        int b = __ldg(batch + n);
        if (b != cur) {
            red_add(&g_pool[cur * HD + 2 * lane], a0);
            red_add(&g_pool[cur * HD + 2 * lane + 1], a1);
            if (lane == 0) red_add(&g_cnt[cur], (float)(n - runStart));
            cur = b; runStart = n; a0 = 0.f; a1 = 0.f;
        }
        float2 f = __half22float2(__ldg(h16 + (size_t)n * 32 + lane));
        a0 += f.x; a1 += f.y;
    }
    red_add(&g_pool[cur * HD + 2 * lane], a0);
    red_add(&g_pool[cur * HD + 2 * lane + 1], a1);
    if (lane == 0) red_add(&g_cnt[cur], (float)(n1 - runStart));
}

// ---------------- MLP head ----------------
__global__ void head_kernel(const float* __restrict__ fc1w, const float* __restrict__ fc1b,
                            const float* __restrict__ fc2w, const float* __restrict__ fc2b,
                            float* __restrict__ out) {
    __shared__ float w1s[64 * 64];
    int tid = threadIdx.x;  // 128
    for (int i = tid; i < 64 * 64; i += 128) w1s[i] = fc1w[i];
    __syncthreads();
    if (tid < NG) {
        float ci = 1.0f / fmaxf(g_cnt[tid], 1.0f);
        float p[64];
#pragma unroll
        for (int f = 0; f < 64; f++) p[f] = g_pool[tid * HD + f] * ci;
        float hid[64];
#pragma unroll
        for (int j = 0; j < 64; j++) {
            float acc = fc1b[j];
#pragma unroll
            for (int f = 0; f < 64; f++) acc = fmaf(p[f], w1s[j * 64 + f], acc);
            hid[j] = fmaxf(acc, 0.f);
        }
#pragma unroll
        for (int u = 0; u < 2; u++) {
            float acc = fc2b[u];
#pragma unroll
            for (int j = 0; j < 64; j++) acc = fmaf(hid[j], __ldg(fc2w + u * 64 + j), acc);
            out[tid * 2 + u] = acc;
        }
    }
}

// ---------------- launch ----------------
extern "C" void kernel_launch(void* const* d_in, const int* in_sizes, int n_in,
                              void* d_out, int out_size) {
    const float* x    = (const float*)d_in[0];
    const int*   ei   = (const int*)d_in[1];
    const int*   src  = ei;
    const int*   dst  = ei + NE;
    const int*   bat  = (const int*)d_in[2];
    const float* w1l  = (const float*)d_in[3];
    const float* b1   = (const float*)d_in[4];
    const float* w1r  = (const float*)d_in[5];
    const float* g1   = (const float*)d_in[6];
    const float* be1  = (const float*)d_in[7];
    const float* w2l  = (const float*)d_in[8];
    const float* b2   = (const float*)d_in[9];
    const float* w2r  = (const float*)d_in[10];
    const float* g2   = (const float*)d_in[11];
    const float* be2  = (const float*)d_in[12];
    const float* w3l  = (const float*)d_in[13];
    const float* b3   = (const float*)d_in[14];
    const float* w3r  = (const float*)d_in[15];
    const float* g3   = (const float*)d_in[16];
    const float* be3  = (const float*)d_in[17];
    const float* fc1w = (const float*)d_in[18];
    const float* fc1b = (const float*)d_in[19];
    const float* fc2w = (const float*)d_in[20];
    const float* fc2b = (const float*)d_in[21];
    float* out = (float*)d_out;

    // CSR build
    zero_small_kernel<<<(NN + 255) / 256, 256>>>();
    hist_kernel<<<(NE + 255) / 256, 256>>>(dst);
    scan_kernel<<<NBLK, SCAN_BLK>>>();
    place_kernel<<<(NE + 255) / 256, 256>>>(src, dst);

    // layer 1
    gather1_kernel<<<(NN * 32 + 255) / 256, 256>>>(x);
    node1_kernel<<<(NN + 255) / 256, 256>>>(x, w1l, b1, w1r);
    cvt_kernel<<<(NN * 8 + 255) / 256, 256>>>(0, g1, be1);

    // layer 2
    gather64_kernel<<<(NN * 32 + 255) / 256, 256>>>(0);
    node64_kernel<<<(NN + 63) / 64, 128>>>(0, w2l, b2, w2r);
    cvt_kernel<<<(NN * 8 + 255) / 256, 256>>>(1, g2, be2);

    // layer 3
    gather64_kernel<<<(NN * 32 + 255) / 256, 256>>>(1);
    node64_kernel<<<(NN + 63) / 64, 128>>>(1, w3l, b3, w3r);
    cvt_kernel<<<(NN * 8 + 255) / 256, 256>>>(2, g3, be3);

    // pool + head
    pool_kernel<<<(NN + 255) / 256, 256>>>(bat);
    head_kernel<<<1, 128>>>(fc1w, fc1b, fc2w, fc2b, out);
}

// round 11
// speedup vs baseline: 1.7629x; 1.0192x over previous
#include <cuda_runtime.h>
#include <cuda_fp16.h>
#include <cstddef>
#include <cstdint>

#define NN 100000
#define NE 3200000
#define NG 128
#define HD 64
#define BN_EPS 1e-5f
#define SCAN_BLK 1024
#define NBLK ((NN + SCAN_BLK - 1) / SCAN_BLK)

// ---------------- scratch (static device globals; no allocation) ----------------
__device__ __align__(16) int   g_count[NN];
__device__ __align__(16) int   g_rowptr[NN + 1];
__device__ __align__(16) int   g_cursor[NN];
__device__ __align__(16) int   g_bsum[NBLK];
__device__ __align__(16) int   g_flag[NBLK];
__device__ __align__(16) int   g_csr[NE];
__device__ __align__(16) float g_deg[NN];            // 1/max(deg,1)
__device__ __align__(16) float g_agg4[NN * 4];
__device__ __align__(16) float g_aggA[(size_t)NN * HD];
__device__ __align__(16) float g_hA[(size_t)NN * HD];   // layer1 pre-BN
__device__ __align__(16) float g_hB[(size_t)NN * HD];   // layer2 pre-BN
__device__ __align__(16) float g_hC[(size_t)NN * HD];   // layer3 pre-BN
__device__ __align__(16) __half g_h16A[(size_t)NN * HD]; // relu(bn1(hA)) fp16
__device__ __align__(16) __half g_h16B[(size_t)NN * HD]; // relu(bn2(hB)) fp16
__device__ __align__(16) __half g_h16C[(size_t)NN * HD]; // relu(bn3(hC)) fp16
__device__ __align__(16) float g_bnsum[3 * HD];
__device__ __align__(16) float g_bnsq[3 * HD];
__device__ __align__(16) float g_pool[NG * HD];
__device__ __align__(16) float g_cnt[NG];

// ---------------- helpers ----------------
__device__ __forceinline__ void red_add(float* p, float v) {
    asm volatile("red.global.add.f32 [%0], %1;" :: "l"(p), "f"(v) : "memory");
}
__device__ __forceinline__ void red_add_i(int* p, int v) {
    asm volatile("red.global.add.s32 [%0], %1;" :: "l"(p), "r"(v) : "memory");
}

// ---------------- zero the small scratch ----------------
__global__ void zero_small_kernel() {
    int i = blockIdx.x * blockDim.x + threadIdx.x;
    if (i < NN) g_count[i] = 0;
    if (i < NBLK) g_flag[i] = 0;
    if (i < NG * HD) g_pool[i] = 0.f;
    if (i < 3 * HD) { g_bnsum[i] = 0.f; g_bnsq[i] = 0.f; }
    if (i < NG) g_cnt[i] = 0.f;
}

// ---------------- CSR build: histogram (fire-and-forget reds) ----------------
__global__ void hist_kernel(const int* __restrict__ dst) {
    int e = blockIdx.x * blockDim.x + threadIdx.x;
    if (e < NE) red_add_i(&g_count[dst[e]], 1);
}

// ---------------- CSR build: single-kernel scan, parallel lookback ----------------
// NBLK = 98 blocks <= 148 SMs -> all co-resident, lookback cannot deadlock.
__global__ void scan_kernel() {
    int bid = blockIdx.x;
    int i = bid * SCAN_BLK + threadIdx.x;
    int lane = threadIdx.x & 31, wid = threadIdx.x >> 5;
    int v = (i < NN) ? g_count[i] : 0;
    int inc = v;
#pragma unroll
    for (int o = 1; o < 32; o <<= 1) {
        int t = __shfl_up_sync(0xffffffffu, inc, o);
        if (lane >= o) inc += t;
    }
    __shared__ int wsum[32];
    __shared__ int blockOff;
    if (lane == 31) wsum[wid] = inc;
    __syncthreads();
    if (wid == 0) {
        int t = wsum[lane];
        int ti = t;
#pragma unroll
        for (int o = 1; o < 32; o <<= 1) {
            int u = __shfl_up_sync(0xffffffffu, ti, o);
            if (lane >= o) ti += u;
        }
        wsum[lane] = ti - t;   // exclusive warp offsets
    }
    __syncthreads();
    int excl = inc - v + wsum[wid];

    // publish block total
    if (threadIdx.x == SCAN_BLK - 1) {
        g_bsum[bid] = excl + v;
        __threadfence();
        atomicExch(&g_flag[bid], 1);
    }
    // parallel lookback: 32 lanes poll predecessors concurrently
    if (wid == 0) {
        int off = 0;
        for (int b = lane; b < bid; b += 32) {
            while (atomicAdd(&g_flag[b], 0) == 0) {}
            off += *((volatile int*)&g_bsum[b]);
        }
#pragma unroll
        for (int o = 16; o; o >>= 1) off += __shfl_xor_sync(0xffffffffu, off, o);
        if (lane == 0) blockOff = off;
    }
    __syncthreads();
    int rp = excl + blockOff;
    if (i < NN) {
        g_rowptr[i] = rp;
        g_cursor[i] = rp;
        g_deg[i] = 1.0f / fmaxf((float)v, 1.0f);
    }
    if (i == NN - 1) g_rowptr[NN] = NE;
}

// ---------------- CSR build: placement ----------------
__global__ void place_kernel(const int* __restrict__ src, const int* __restrict__ dst) {
    int e = blockIdx.x * blockDim.x + threadIdx.x;
    if (e >= NE) return;
    int pos = atomicAdd(&g_cursor[dst[e]], 1);
    g_csr[pos] = src[e];
}

// ---------------- layer-1 gather (4-dim): warp per node, 2 lanes/edge ----------------
// 16 edges served by one shuffle + one LDG.64 per lane round.
__global__ void gather1_kernel(const float* __restrict__ x) {
    int wi = (blockIdx.x * blockDim.x + threadIdx.x) >> 5;
    if (wi >= NN) return;
    int lane = threadIdx.x & 31;
    int grp = lane >> 1;          // edge offset within 16-edge round
    int cp = lane & 1;            // column pair: cols 2cp, 2cp+1
    int beg = g_rowptr[wi], end = g_rowptr[wi + 1];
    float ax = 0.f, ay = 0.f;
    for (int base = beg; base < end; base += 32) {
        int idx = base + lane;
        int sv = (idx < end) ? __ldg(g_csr + idx) : 0;
        int m = end - base; if (m > 32) m = 32;
#pragma unroll 2
        for (int j = 0; j < m; j += 16) {
            int e = j + grp;
            int s = __shfl_sync(0xffffffffu, sv, e);
            float2 v = __ldg((const float2*)(x + 4 * (size_t)s + 2 * cp));
            if (e < m) { ax += v.x; ay += v.y; }
        }
    }
#pragma unroll
    for (int o = 2; o <= 16; o <<= 1) {
        ax += __shfl_xor_sync(0xffffffffu, ax, o);
        ay += __shfl_xor_sync(0xffffffffu, ay, o);
    }
    if (lane < 2) *(float2*)(g_agg4 + 4 * (size_t)wi + 2 * cp) = make_float2(ax, ay);
}

// ---------------- layer-1 node transform + BN stats ----------------
__global__ void node1_kernel(const float* __restrict__ x, const float* __restrict__ wl,
                             const float* __restrict__ b, const float* __restrict__ wr) {
    __shared__ float wls[HD * 4], wrs[HD * 4], bs[HD];
    int tid = threadIdx.x;
    if (tid < HD * 4) { wls[tid] = wl[tid]; wrs[tid] = wr[tid]; }
    if (tid < HD) bs[tid] = b[tid];
    __syncthreads();

    int n = blockIdx.x * blockDim.x + tid;
    bool act = n < NN;
    float di = act ? g_deg[n] : 0.f;
    float4 a = act ? *(const float4*)(g_agg4 + 4 * (size_t)n) : make_float4(0, 0, 0, 0);
    a.x *= di; a.y *= di; a.z *= di; a.w *= di;
    float4 xv = act ? __ldg((const float4*)(x + 4 * (size_t)n)) : make_float4(0, 0, 0, 0);
    int lane = tid & 31;

#pragma unroll
    for (int fb = 0; fb < 16; fb++) {
        float o[4];
#pragma unroll
        for (int j = 0; j < 4; j++) {
            int f = fb * 4 + j;
            float acc = bs[f];
            acc = fmaf(a.x, wls[f * 4 + 0], acc);
            acc = fmaf(a.y, wls[f * 4 + 1], acc);
            acc = fmaf(a.z, wls[f * 4 + 2], acc);
            acc = fmaf(a.w, wls[f * 4 + 3], acc);
            acc = fmaf(xv.x, wrs[f * 4 + 0], acc);
            acc = fmaf(xv.y, wrs[f * 4 + 1], acc);
            acc = fmaf(xv.z, wrs[f * 4 + 2], acc);
            acc = fmaf(xv.w, wrs[f * 4 + 3], acc);
            o[j] = acc;
        }
        if (act) *(float4*)(g_hA + (size_t)n * HD + fb * 4) = make_float4(o[0], o[1], o[2], o[3]);
#pragma unroll
        for (int j = 0; j < 4; j++) {
            float h = act ? o[j] : 0.f;
            float s = h, q = h * h;
#pragma unroll
            for (int off = 16; off; off >>= 1) {
                s += __shfl_xor_sync(0xffffffffu, s, off);
                q += __shfl_xor_sync(0xffffffffu, q, off);
            }
            if (lane == 0) {
                red_add(&g_bnsum[fb * 4 + j], s);
                red_add(&g_bnsq[fb * 4 + j], q);
            }
        }
    }
}

// ---------------- convert: h_pre -> fp16 relu(bn(h)); BN finalize done in-block ----------------
__global__ void cvt_kernel(int which, const float* __restrict__ gamma,
                           const float* __restrict__ beta) {
    const float* __restrict__ hin = (which == 0) ? g_hA : (which == 1) ? g_hB : g_hC;
    __half* __restrict__ hout = (which == 0) ? g_h16A : (which == 1) ? g_h16B : g_h16C;
    __shared__ float sc_s[HD], sh_s[HD];
    int tid = threadIdx.x;
    if (tid < HD) {
        const float invn = 1.0f / (float)NN;
        float m = g_bnsum[which * HD + tid] * invn;
        float v = g_bnsq[which * HD + tid] * invn - m * m;
        float s = __ldg(gamma + tid) * rsqrtf(v + BN_EPS);
        sc_s[tid] = s;
        sh_s[tid] = __ldg(beta + tid) - m * s;
    }
    __syncthreads();
    int t = blockIdx.x * blockDim.x + tid;
    if (t >= NN * 8) return;
    int n = t >> 3, c = (t & 7) * 8;
    float4 v0 = __ldg((const float4*)(hin + (size_t)n * HD + c));
    float4 v1 = __ldg((const float4*)(hin + (size_t)n * HD + c + 4));
    float r0 = fmaxf(fmaf(v0.x, sc_s[c + 0], sh_s[c + 0]), 0.f);
    float r1 = fmaxf(fmaf(v0.y, sc_s[c + 1], sh_s[c + 1]), 0.f);
    float r2 = fmaxf(fmaf(v0.z, sc_s[c + 2], sh_s[c + 2]), 0.f);
    float r3 = fmaxf(fmaf(v0.w, sc_s[c + 3], sh_s[c + 3]), 0.f);
    float r4 = fmaxf(fmaf(v1.x, sc_s[c + 4], sh_s[c + 4]), 0.f);
    float r5 = fmaxf(fmaf(v1.y, sc_s[c + 5], sh_s[c + 5]), 0.f);
    float r6 = fmaxf(fmaf(v1.z, sc_s[c + 6], sh_s[c + 6]), 0.f);
    float r7 = fmaxf(fmaf(v1.w, sc_s[c + 7], sh_s[c + 7]), 0.f);
    __half2* dst = (__half2*)(hout + (size_t)n * HD + c);
    dst[0] = __floats2half2_rn(r0, r1);
    dst[1] = __floats2half2_rn(r2, r3);
    dst[2] = __floats2half2_rn(r4, r5);
    dst[3] = __floats2half2_rn(r6, r7);
}

// ---------------- 64-wide gather over fp16: warp/node, halves do even/odd edges ----------------
// Lane l: half = l>>4 (even/odd edge), hl = l&15 (cols 4hl..4hl+3, one uint2 = 8B).
// One shuffle + one LDG.64 serves 2 edges. fp16 accumulate within 32-edge chunk,
// fp32 across chunks, cross-half combine at the end.
__global__ void gather64_kernel(int which) {
    const __half* __restrict__ hin = (which == 0) ? g_h16A : g_h16B;
    int wi = (blockIdx.x * blockDim.x + threadIdx.x) >> 5;
    if (wi >= NN) return;
    int lane = threadIdx.x & 31;
    int half = lane >> 4;
    int hl = lane & 15;
    int beg = g_rowptr[wi], end = g_rowptr[wi + 1];
    float a0 = 0.f, a1 = 0.f, a2 = 0.f, a3 = 0.f;
    const __half2 hz = __float2half2_rn(0.f);
    for (int base = beg; base < end; base += 32) {
        int idx = base + lane;
        int sv = (idx < end) ? __ldg(g_csr + idx) : 0;
        int m = end - base; if (m > 32) m = 32;
        __half2 h0 = hz, h1 = hz;
#pragma unroll 8
        for (int j = 0; j < m; j += 2) {
            int e = j + half;
            int s = __shfl_sync(0xffffffffu, sv, e);
            uint2 p = __ldg((const uint2*)(hin + (size_t)s * HD + 4 * hl));
            __half2 v0 = *reinterpret_cast<__half2*>(&p.x);
            __half2 v1 = *reinterpret_cast<__half2*>(&p.y);
            if (e < m) { h0 = __hadd2(h0, v0); h1 = __hadd2(h1, v1); }
        }
        float2 f0 = __half22float2(h0), f1 = __half22float2(h1);
        a0 += f0.x; a1 += f0.y; a2 += f1.x; a3 += f1.y;
    }
    a0 += __shfl_xor_sync(0xffffffffu, a0, 16);
    a1 += __shfl_xor_sync(0xffffffffu, a1, 16);
    a2 += __shfl_xor_sync(0xffffffffu, a2, 16);
    a3 += __shfl_xor_sync(0xffffffffu, a3, 16);
    if (half == 0)
        *(float4*)(g_aggA + (size_t)wi * HD + 4 * hl) = make_float4(a0, a1, a2, a3);
}

// ---------------- layer 2/3 node transform: tensor-core GEMM + BN stats ----------------
// 128 threads (4 warps), 64 nodes/block. One fused K=128 GEMM:
//   h = [deg_inv*agg | h16_prev] (64x128 fp16)  @  [Wl | Wr]^T (128x64 fp16), fp32 accum.
__global__ void node64_kernel(int which, const float* __restrict__ wl,
                              const float* __restrict__ bias, const float* __restrict__ wr) {
    const __half* __restrict__ h16in = (which == 0) ? g_h16A : g_h16B;
    float* __restrict__ hout = (which == 0) ? g_hB : g_hC;
    int stat = which + 1;

    __shared__ __align__(16) __half in_s[64 * 136];   // 64 rows x (128 + 8 pad)
    __shared__ __align__(16) __half w_s[64 * 136];    // 64 f-rows x (128 + 8 pad)

    int tid = threadIdx.x;
    int base = blockIdx.x * 64;

    // fill weights: w_s[f][k] = Wcat[f][k]  (k<64: wl, else wr)
    for (int i = tid; i < 64 * 16; i += 128) {
        int f = i >> 4, c8 = (i & 15) * 8;
        const float* sp = (c8 < 64) ? (wl + f * 64 + c8) : (wr + f * 64 + (c8 - 64));
        float4 u = __ldg((const float4*)sp);
        float4 v = __ldg((const float4*)(sp + 4));
        __half2* dst = (__half2*)(w_s + f * 136 + c8);
        dst[0] = __floats2half2_rn(u.x, u.y);
        dst[1] = __floats2half2_rn(u.z, u.w);
        dst[2] = __floats2half2_rn(v.x, v.y);
        dst[3] = __floats2half2_rn(v.z, v.w);
    }
    // fill inputs: cols 0-63 = deg_inv*agg (fp32->fp16), 64-127 = h16 prev (copy)
    for (int i = tid; i < 64 * 16; i += 128) {
        int n = i >> 4, c8 = (i & 15) * 8;
        int gn = base + n;
        __half2 h0, h1, h2, h3;
        if (gn < NN) {
            if (c8 < 64) {
                float di = g_deg[gn];
                float4 u = __ldg((const float4*)(g_aggA + (size_t)gn * HD + c8));
                float4 v = __ldg((const float4*)(g_aggA + (size_t)gn * HD + c8 + 4));
                h0 = __floats2half2_rn(u.x * di, u.y * di);
                h1 = __floats2half2_rn(u.z * di, u.w * di);
                h2 = __floats2half2_rn(v.x * di, v.y * di);
                h3 = __floats2half2_rn(v.z * di, v.w * di);
            } else {
                const __half2* sp = (const __half2*)(h16in + (size_t)gn * HD + (c8 - 64));
                h0 = sp[0]; h1 = sp[1]; h2 = sp[2]; h3 = sp[3];
            }
        } else {
            h0 = h1 = h2 = h3 = __floats2half2_rn(0.f, 0.f);
        }
        __half2* dst = (__half2*)(in_s + n * 136 + c8);
        dst[0] = h0; dst[1] = h1; dst[2] = h2; dst[3] = h3;
    }
    __syncthreads();

    int lane = tid & 31, w = tid >> 5;
    int g = lane >> 2, iq = lane & 3;
    int row0 = 16 * w + g;            // local row for c0/c1 (row0+8 for c2/c3)

    float c[8][4];
#pragma unroll
    for (int nt = 0; nt < 8; nt++)
#pragma unroll
        for (int r = 0; r < 4; r++) c[nt][r] = 0.f;

    const __half* As  = in_s + row0 * 136;
    const __half* As8 = in_s + (row0 + 8) * 136;
#pragma unroll
    for (int kt = 0; kt < 8; kt++) {
        int k0 = kt * 16 + 2 * iq;
        uint32_t a0 = *(const uint32_t*)(As  + k0);
        uint32_t a1 = *(const uint32_t*)(As8 + k0);
        uint32_t a2 = *(const uint32_t*)(As  + k0 + 8);
        uint32_t a3 = *(const uint32_t*)(As8 + k0 + 8);
#pragma unroll
        for (int nt = 0; nt < 8; nt++) {
            const __half* Bs = w_s + (nt * 8 + g) * 136;
            uint32_t b0 = *(const uint32_t*)(Bs + k0);
            uint32_t b1 = *(const uint32_t*)(Bs + k0 + 8);
            asm volatile(
                "mma.sync.aligned.m16n8k16.row.col.f32.f16.f16.f32 "
                "{%0,%1,%2,%3}, {%4,%5,%6,%7}, {%8,%9}, {%0,%1,%2,%3};"
                : "+f"(c[nt][0]), "+f"(c[nt][1]), "+f"(c[nt][2]), "+f"(c[nt][3])
                : "r"(a0), "r"(a1), "r"(a2), "r"(a3), "r"(b0), "r"(b1));
        }
    }

    // epilogue: bias add, store pre-BN h, BN stats
    int gn0 = base + row0;
    int gn8 = gn0 + 8;
    bool v0 = gn0 < NN, v8 = gn8 < NN;
#pragma unroll
    for (int nt = 0; nt < 8; nt++) {
        int col = nt * 8 + 2 * iq;
        float b0v = __ldg(bias + col), b1v = __ldg(bias + col + 1);
        float h0 = c[nt][0] + b0v, h1 = c[nt][1] + b1v;
        float h2 = c[nt][2] + b0v, h3 = c[nt][3] + b1v;
        if (v0) *(float2*)(hout + (size_t)gn0 * HD + col) = make_float2(h0, h1);
        if (v8) *(float2*)(hout + (size_t)gn8 * HD + col) = make_float2(h2, h3);
        float ps0 = (v0 ? h0 : 0.f) + (v8 ? h2 : 0.f);
        float ps1 = (v0 ? h1 : 0.f) + (v8 ? h3 : 0.f);
        float qs0 = (v0 ? h0 * h0 : 0.f) + (v8 ? h2 * h2 : 0.f);
        float qs1 = (v0 ? h1 * h1 : 0.f) + (v8 ? h3 * h3 : 0.f);
#pragma unroll
        for (int o = 4; o < 32; o <<= 1) {
            ps0 += __shfl_xor_sync(0xffffffffu, ps0, o);
            ps1 += __shfl_xor_sync(0xffffffffu, ps1, o);
            qs0 += __shfl_xor_sync(0xffffffffu, qs0, o);
            qs1 += __shfl_xor_sync(0xffffffffu, qs1, o);
        }
        if (g == 0) {
            red_add(&g_bnsum[stat * HD + col],     ps0);
            red_add(&g_bnsum[stat * HD + col + 1], ps1);
            red_add(&g_bnsq[stat * HD + col],      qs0);
            red_add(&g_bnsq[stat * HD + col + 1],  qs1);
        }
    }
}

// ---------------- mean-pool over graphs (sorted batch -> run-flush) ----------------
__global__ void pool_kernel(const int* __restrict__ batch) {
    const __half2* __restrict__ h16 = (const __half2*)g_h16C;
    int warp = (blockIdx.x * blockDim.x + threadIdx.x) >> 5;
    const int nwarps = NN / 32;  // 3125
    if (warp >= nwarps) return;
    int lane = threadIdx.x & 31;
    int n0 = warp * 32, n1 = n0 + 32;
    int cur = __ldg(batch + n0);
    int runStart = n0;
    float a0 = 0.f, a1 = 0.f;
    for (int n = n0; n < n1; n++) {
        int b = __ldg(batch + n);
        if (b != cur) {
            red_add(&g_pool[cur * HD + 2 * lane], a0);
            red_add(&g_pool[cur * HD + 2 * lane + 1], a1);
            if (lane == 0) red_add(&g_cnt[cur], (float)(n - runStart));
            cur = b; runStart = n; a0 = 0.f; a1 = 0.f;
        }
        float2 f = __half22float2(__ldg(h16 + (size_t)n * 32 + lane));
        a0 += f.x; a1 += f.y;
    }
    red_add(&g_pool[cur * HD + 2 * lane], a0);
    red_add(&g_pool[cur * HD + 2 * lane + 1], a1);
    if (lane == 0) red_add(&g_cnt[cur], (float)(n1 - runStart));
}

// ---------------- MLP head ----------------
__global__ void head_kernel(const float* __restrict__ fc1w, const float* __restrict__ fc1b,
                            const float* __restrict__ fc2w, const float* __restrict__ fc2b,
                            float* __restrict__ out) {
    __shared__ float w1s[64 * 64];
    int tid = threadIdx.x;  // 128
    for (int i = tid; i < 64 * 64; i += 128) w1s[i] = fc1w[i];
    __syncthreads();
    if (tid < NG) {
        float ci = 1.0f / fmaxf(g_cnt[tid], 1.0f);
        float p[64];
#pragma unroll
        for (int f = 0; f < 64; f++) p[f] = g_pool[tid * HD + f] * ci;
        float hid[64];
#pragma unroll
        for (int j = 0; j < 64; j++) {
            float acc = fc1b[j];
#pragma unroll
            for (int f = 0; f < 64; f++) acc = fmaf(p[f], w1s[j * 64 + f], acc);
            hid[j] = fmaxf(acc, 0.f);
        }
#pragma unroll
        for (int u = 0; u < 2; u++) {
            float acc = fc2b[u];
#pragma unroll
            for (int j = 0; j < 64; j++) acc = fmaf(hid[j], __ldg(fc2w + u * 64 + j), acc);
            out[tid * 2 + u] = acc;
        }
    }
}

// ---------------- launch ----------------
extern "C" void kernel_launch(void* const* d_in, const int* in_sizes, int n_in,
                              void* d_out, int out_size) {
    const float* x    = (const float*)d_in[0];
    const int*   ei   = (const int*)d_in[1];
    const int*   src  = ei;
    const int*   dst  = ei + NE;
    const int*   bat  = (const int*)d_in[2];
    const float* w1l  = (const float*)d_in[3];
    const float* b1   = (const float*)d_in[4];
    const float* w1r  = (const float*)d_in[5];
    const float* g1   = (const float*)d_in[6];
    const float* be1  = (const float*)d_in[7];
    const float* w2l  = (const float*)d_in[8];
    const float* b2   = (const float*)d_in[9];
    const float* w2r  = (const float*)d_in[10];
    const float* g2   = (const float*)d_in[11];
    const float* be2  = (const float*)d_in[12];
    const float* w3l  = (const float*)d_in[13];
    const float* b3   = (const float*)d_in[14];
    const float* w3r  = (const float*)d_in[15];
    const float* g3   = (const float*)d_in[16];
    const float* be3  = (const float*)d_in[17];
    const float* fc1w = (const float*)d_in[18];
    const float* fc1b = (const float*)d_in[19];
    const float* fc2w = (const float*)d_in[20];
    const float* fc2b = (const float*)d_in[21];
    float* out = (float*)d_out;

    // CSR build
    zero_small_kernel<<<(NN + 255) / 256, 256>>>();
    hist_kernel<<<(NE + 255) / 256, 256>>>(dst);
    scan_kernel<<<NBLK, SCAN_BLK>>>();
    place_kernel<<<(NE + 255) / 256, 256>>>(src, dst);

    // layer 1
    gather1_kernel<<<(NN * 32 + 255) / 256, 256>>>(x);
    node1_kernel<<<(NN + 255) / 256, 256>>>(x, w1l, b1, w1r);
    cvt_kernel<<<(NN * 8 + 255) / 256, 256>>>(0, g1, be1);

    // layer 2
    gather64_kernel<<<(NN * 32 + 255) / 256, 256>>>(0);
    node64_kernel<<<(NN + 63) / 64, 128>>>(0, w2l, b2, w2r);
    cvt_kernel<<<(NN * 8 + 255) / 256, 256>>>(1, g2, be2);

    // layer 3
    gather64_kernel<<<(NN * 32 + 255) / 256, 256>>>(1);
    node64_kernel<<<(NN + 63) / 64, 128>>>(1, w3l, b3, w3r);
    cvt_kernel<<<(NN * 8 + 255) / 256, 256>>>(2, g3, be3);

    // pool + head
    pool_kernel<<<(NN + 255) / 256, 256>>>(bat);
    head_kernel<<<1, 128>>>(fc1w, fc1b, fc2w, fc2b, out);
}

// round 12
// speedup vs baseline: 1.8759x; 1.0641x over previous
#include <cuda_runtime.h>
#include <cuda_fp16.h>
#include <cstddef>
#include <cstdint>

#define NN 100000
#define NE 3200000
#define NG 128
#define HD 64
#define BN_EPS 1e-5f
#define SCAN_BLK 1024
#define NBLK ((NN + SCAN_BLK - 1) / SCAN_BLK)

// ---------------- scratch (static device globals; no allocation) ----------------
__device__ __align__(16) int   g_count[NN];
__device__ __align__(16) int   g_rowptr[NN + 1];
__device__ __align__(16) int   g_cursor[NN];
__device__ __align__(16) int   g_bsum[NBLK];
__device__ __align__(16) int   g_flag[NBLK];
__device__ __align__(16) int   g_csr[NE];
__device__ __align__(16) float g_deg[NN];              // 1/max(deg,1)
__device__ __align__(16) float g_agg4[NN * 4];
__device__ __align__(16) __half g_hpre[(size_t)NN * HD]; // pre-BN h (fp16), reused per layer
__device__ __align__(16) __half g_h16A[(size_t)NN * HD]; // relu(bn1(h1)) fp16
__device__ __align__(16) __half g_h16B[(size_t)NN * HD]; // relu(bn2(h2)) fp16
__device__ __align__(16) __half g_h16C[(size_t)NN * HD]; // relu(bn3(h3)) fp16
__device__ __align__(16) float g_bnsum[3 * HD];
__device__ __align__(16) float g_bnsq[3 * HD];
__device__ __align__(16) float g_pool[NG * HD];
__device__ __align__(16) float g_cnt[NG];

// ---------------- helpers ----------------
__device__ __forceinline__ void red_add(float* p, float v) {
    asm volatile("red.global.add.f32 [%0], %1;" :: "l"(p), "f"(v) : "memory");
}
__device__ __forceinline__ void red_add_i(int* p, int v) {
    asm volatile("red.global.add.s32 [%0], %1;" :: "l"(p), "r"(v) : "memory");
}
__device__ __forceinline__ unsigned h2u(__half2 h) {
    return *reinterpret_cast<unsigned*>(&h);
}
__device__ __forceinline__ __half2 u2h(unsigned u) {
    return *reinterpret_cast<__half2*>(&u);
}

// ---------------- zero the small scratch ----------------
__global__ void zero_small_kernel() {
    int i = blockIdx.x * blockDim.x + threadIdx.x;
    if (i < NN) g_count[i] = 0;
    if (i < NBLK) g_flag[i] = 0;
    if (i < NG * HD) g_pool[i] = 0.f;
    if (i < 3 * HD) { g_bnsum[i] = 0.f; g_bnsq[i] = 0.f; }
    if (i < NG) g_cnt[i] = 0.f;
}

// ---------------- CSR build: histogram (fire-and-forget reds) ----------------
__global__ void hist_kernel(const int* __restrict__ dst) {
    int e = blockIdx.x * blockDim.x + threadIdx.x;
    if (e < NE) red_add_i(&g_count[dst[e]], 1);
}

// ---------------- CSR build: single-kernel scan, parallel lookback ----------------
__global__ void scan_kernel() {
    int bid = blockIdx.x;
    int i = bid * SCAN_BLK + threadIdx.x;
    int lane = threadIdx.x & 31, wid = threadIdx.x >> 5;
    int v = (i < NN) ? g_count[i] : 0;
    int inc = v;
#pragma unroll
    for (int o = 1; o < 32; o <<= 1) {
        int t = __shfl_up_sync(0xffffffffu, inc, o);
        if (lane >= o) inc += t;
    }
    __shared__ int wsum[32];
    __shared__ int blockOff;
    if (lane == 31) wsum[wid] = inc;
    __syncthreads();
    if (wid == 0) {
        int t = wsum[lane];
        int ti = t;
#pragma unroll
        for (int o = 1; o < 32; o <<= 1) {
            int u = __shfl_up_sync(0xffffffffu, ti, o);
            if (lane >= o) ti += u;
        }
        wsum[lane] = ti - t;
    }
    __syncthreads();
    int excl = inc - v + wsum[wid];

    if (threadIdx.x == SCAN_BLK - 1) {
        g_bsum[bid] = excl + v;
        __threadfence();
        atomicExch(&g_flag[bid], 1);
    }
    if (wid == 0) {
        int off = 0;
        for (int b = lane; b < bid; b += 32) {
            while (atomicAdd(&g_flag[b], 0) == 0) {}
            off += *((volatile int*)&g_bsum[b]);
        }
#pragma unroll
        for (int o = 16; o; o >>= 1) off += __shfl_xor_sync(0xffffffffu, off, o);
        if (lane == 0) blockOff = off;
    }
    __syncthreads();
    int rp = excl + blockOff;
    if (i < NN) {
        g_rowptr[i] = rp;
        g_cursor[i] = rp;
        g_deg[i] = 1.0f / fmaxf((float)v, 1.0f);
    }
    if (i == NN - 1) g_rowptr[NN] = NE;
}

// ---------------- CSR build: placement ----------------
__global__ void place_kernel(const int* __restrict__ src, const int* __restrict__ dst) {
    int e = blockIdx.x * blockDim.x + threadIdx.x;
    if (e >= NE) return;
    int pos = atomicAdd(&g_cursor[dst[e]], 1);
    g_csr[pos] = src[e];
}

// ---------------- layer-1 gather (4-dim): warp per node, 2 lanes/edge ----------------
__global__ void gather1_kernel(const float* __restrict__ x) {
    int wi = (blockIdx.x * blockDim.x + threadIdx.x) >> 5;
    if (wi >= NN) return;
    int lane = threadIdx.x & 31;
    int grp = lane >> 1;
    int cp = lane & 1;
    int beg = g_rowptr[wi], end = g_rowptr[wi + 1];
    float ax = 0.f, ay = 0.f;
    for (int base = beg; base < end; base += 32) {
        int idx = base + lane;
        int sv = (idx < end) ? __ldg(g_csr + idx) : 0;
        int m = end - base; if (m > 32) m = 32;
#pragma unroll 2
        for (int j = 0; j < m; j += 16) {
            int e = j + grp;
            int s = __shfl_sync(0xffffffffu, sv, e);
            float2 v = __ldg((const float2*)(x + 4 * (size_t)s + 2 * cp));
            if (e < m) { ax += v.x; ay += v.y; }
        }
    }
#pragma unroll
    for (int o = 2; o <= 16; o <<= 1) {
        ax += __shfl_xor_sync(0xffffffffu, ax, o);
        ay += __shfl_xor_sync(0xffffffffu, ay, o);
    }
    if (lane < 2) *(float2*)(g_agg4 + 4 * (size_t)wi + 2 * cp) = make_float2(ax, ay);
}

// ---------------- layer-1 node transform + BN stats (pre-BN h -> fp16) ----------------
__global__ void node1_kernel(const float* __restrict__ x, const float* __restrict__ wl,
                             const float* __restrict__ b, const float* __restrict__ wr) {
    __shared__ float wls[HD * 4], wrs[HD * 4], bs[HD];
    int tid = threadIdx.x;
    if (tid < HD * 4) { wls[tid] = wl[tid]; wrs[tid] = wr[tid]; }
    if (tid < HD) bs[tid] = b[tid];
    __syncthreads();

    int n = blockIdx.x * blockDim.x + tid;
    bool act = n < NN;
    float di = act ? g_deg[n] : 0.f;
    float4 a = act ? *(const float4*)(g_agg4 + 4 * (size_t)n) : make_float4(0, 0, 0, 0);
    a.x *= di; a.y *= di; a.z *= di; a.w *= di;
    float4 xv = act ? __ldg((const float4*)(x + 4 * (size_t)n)) : make_float4(0, 0, 0, 0);
    int lane = tid & 31;

#pragma unroll
    for (int fb = 0; fb < 16; fb++) {
        float o[4];
#pragma unroll
        for (int j = 0; j < 4; j++) {
            int f = fb * 4 + j;
            float acc = bs[f];
            acc = fmaf(a.x, wls[f * 4 + 0], acc);
            acc = fmaf(a.y, wls[f * 4 + 1], acc);
            acc = fmaf(a.z, wls[f * 4 + 2], acc);
            acc = fmaf(a.w, wls[f * 4 + 3], acc);
            acc = fmaf(xv.x, wrs[f * 4 + 0], acc);
            acc = fmaf(xv.y, wrs[f * 4 + 1], acc);
            acc = fmaf(xv.z, wrs[f * 4 + 2], acc);
            acc = fmaf(xv.w, wrs[f * 4 + 3], acc);
            o[j] = acc;
        }
        if (act) {
            unsigned p0 = h2u(__floats2half2_rn(o[0], o[1]));
            unsigned p1 = h2u(__floats2half2_rn(o[2], o[3]));
            *(uint2*)(g_hpre + (size_t)n * HD + fb * 4) = make_uint2(p0, p1);
        }
#pragma unroll
        for (int j = 0; j < 4; j++) {
            float h = act ? o[j] : 0.f;
            float s = h, q = h * h;
#pragma unroll
            for (int off = 16; off; off >>= 1) {
                s += __shfl_xor_sync(0xffffffffu, s, off);
                q += __shfl_xor_sync(0xffffffffu, q, off);
            }
            if (lane == 0) {
                red_add(&g_bnsum[fb * 4 + j], s);
                red_add(&g_bnsq[fb * 4 + j], q);
            }
        }
    }
}

// ---------------- convert: g_hpre (fp16 pre-BN) -> fp16 relu(bn(h)); BN finalize in-block ----------------
__global__ void cvt_kernel(int which, const float* __restrict__ gamma,
                           const float* __restrict__ beta) {
    __half* __restrict__ hout = (which == 0) ? g_h16A : (which == 1) ? g_h16B : g_h16C;
    __shared__ float sc_s[HD], sh_s[HD];
    int tid = threadIdx.x;
    if (tid < HD) {
        const float invn = 1.0f / (float)NN;
        float m = g_bnsum[which * HD + tid] * invn;
        float v = g_bnsq[which * HD + tid] * invn - m * m;
        float s = __ldg(gamma + tid) * rsqrtf(v + BN_EPS);
        sc_s[tid] = s;
        sh_s[tid] = __ldg(beta + tid) - m * s;
    }
    __syncthreads();
    int t = blockIdx.x * blockDim.x + tid;
    if (t >= NN * 8) return;
    int n = t >> 3, c = (t & 7) * 8;
    uint4 raw = *(const uint4*)(g_hpre + (size_t)n * HD + c);
    float2 f0 = __half22float2(u2h(raw.x));
    float2 f1 = __half22float2(u2h(raw.y));
    float2 f2 = __half22float2(u2h(raw.z));
    float2 f3 = __half22float2(u2h(raw.w));
    float r0 = fmaxf(fmaf(f0.x, sc_s[c + 0], sh_s[c + 0]), 0.f);
    float r1 = fmaxf(fmaf(f0.y, sc_s[c + 1], sh_s[c + 1]), 0.f);
    float r2 = fmaxf(fmaf(f1.x, sc_s[c + 2], sh_s[c + 2]), 0.f);
    float r3 = fmaxf(fmaf(f1.y, sc_s[c + 3], sh_s[c + 3]), 0.f);
    float r4 = fmaxf(fmaf(f2.x, sc_s[c + 4], sh_s[c + 4]), 0.f);
    float r5 = fmaxf(fmaf(f2.y, sc_s[c + 5], sh_s[c + 5]), 0.f);
    float r6 = fmaxf(fmaf(f3.x, sc_s[c + 6], sh_s[c + 6]), 0.f);
    float r7 = fmaxf(fmaf(f3.y, sc_s[c + 7], sh_s[c + 7]), 0.f);
    uint4 outp;
    outp.x = h2u(__floats2half2_rn(r0, r1));
    outp.y = h2u(__floats2half2_rn(r2, r3));
    outp.z = h2u(__floats2half2_rn(r4, r5));
    outp.w = h2u(__floats2half2_rn(r6, r7));
    *(uint4*)(hout + (size_t)n * HD + c) = outp;
}

// ---------------- layers 2/3: fused gather + tensor-core transform + BN stats ----------------
// 256 threads (8 warps), 64 nodes/block.
// Phase A: warp w gathers nodes w*8..w*8+7 directly into in_s as fp16
//          (cols 0-63 = deg_inv * sum of neighbor h16; cols 64-127 = own h16).
// Phase B: 8 warps MMA 64x128 @ 128x64: warp (w&3) does rows 16(w&3)..+16,
//          n-tile half (w>>2) covers 4 of 8 tiles. fp32 accum, bias, fp16 store, BN stats.
__global__ void layer23_kernel(int which, const float* __restrict__ wl,
                               const float* __restrict__ bias, const float* __restrict__ wr) {
    const __half2* __restrict__ hin = (const __half2*)((which == 0) ? g_h16A : g_h16B);
    int stat = which + 1;

    __shared__ __align__(16) __half in_s[64 * 136];
    __shared__ __align__(16) __half w_s[64 * 136];

    int tid = threadIdx.x;
    int base = blockIdx.x * 64;
    int w = tid >> 5, lane = tid & 31;

    // weights fill: w_s[f][k] = Wcat[f][k]  (k<64: wl, else wr)
    for (int i = tid; i < 64 * 16; i += 256) {
        int f = i >> 4, c8 = (i & 15) * 8;
        const float* sp = (c8 < 64) ? (wl + f * 64 + c8) : (wr + f * 64 + (c8 - 64));
        float4 u = __ldg((const float4*)sp);
        float4 v = __ldg((const float4*)(sp + 4));
        __half2* dst = (__half2*)(w_s + f * 136 + c8);
        dst[0] = __floats2half2_rn(u.x, u.y);
        dst[1] = __floats2half2_rn(u.z, u.w);
        dst[2] = __floats2half2_rn(v.x, v.y);
        dst[3] = __floats2half2_rn(v.z, v.w);
    }

    // gather phase: lane owns cols 2l,2l+1 (one half2)
#pragma unroll 1
    for (int k = 0; k < 8; k++) {
        int n = w * 8 + k;
        int gn = base + n;
        float a0 = 0.f, a1 = 0.f;
        __half2 prev = __float2half2_rn(0.f);
        if (gn < NN) {
            int beg = g_rowptr[gn], end = g_rowptr[gn + 1];
            for (int cb = beg; cb < end; cb += 32) {
                int idx = cb + lane;
                int sv = (idx < end) ? __ldg(g_csr + idx) : 0;
                int m = end - cb; if (m > 32) m = 32;
                int j = 0;
                for (; j + 4 <= m; j += 4) {
                    int s0 = __shfl_sync(0xffffffffu, sv, j + 0);
                    int s1 = __shfl_sync(0xffffffffu, sv, j + 1);
                    int s2 = __shfl_sync(0xffffffffu, sv, j + 2);
                    int s3 = __shfl_sync(0xffffffffu, sv, j + 3);
                    float2 f0 = __half22float2(__ldcg(hin + (size_t)s0 * 32 + lane));
                    float2 f1 = __half22float2(__ldcg(hin + (size_t)s1 * 32 + lane));
                    float2 f2 = __half22float2(__ldcg(hin + (size_t)s2 * 32 + lane));
                    float2 f3 = __half22float2(__ldcg(hin + (size_t)s3 * 32 + lane));
                    a0 += f0.x + f1.x; a1 += f0.y + f1.y;
                    a0 += f2.x + f3.x; a1 += f2.y + f3.y;
                }
                for (; j < m; j++) {
                    int s = __shfl_sync(0xffffffffu, sv, j);
                    float2 f = __half22float2(__ldcg(hin + (size_t)s * 32 + lane));
                    a0 += f.x; a1 += f.y;
                }
            }
            float di = g_deg[gn];
            a0 *= di; a1 *= di;
            prev = __ldg(hin + (size_t)gn * 32 + lane);
        }
        *(__half2*)(in_s + n * 136 + 2 * lane) = __floats2half2_rn(a0, a1);
        *(__half2*)(in_s + n * 136 + 64 + 2 * lane) = prev;
    }
    __syncthreads();

    // MMA phase: all 8 warps; warp covers rows 16*(w&3).. and 4 n-tiles (w>>2 half)
    int w4 = w & 3, nh = w >> 2;
    int g = lane >> 2, iq = lane & 3;
    int row0 = 16 * w4 + g;

    float c[4][4];
#pragma unroll
    for (int nt = 0; nt < 4; nt++)
#pragma unroll
        for (int r = 0; r < 4; r++) c[nt][r] = 0.f;

    const __half* As  = in_s + row0 * 136;
    const __half* As8 = in_s + (row0 + 8) * 136;
#pragma unroll
    for (int kt = 0; kt < 8; kt++) {
        int k0 = kt * 16 + 2 * iq;
        uint32_t a0 = *(const uint32_t*)(As  + k0);
        uint32_t a1 = *(const uint32_t*)(As8 + k0);
        uint32_t a2 = *(const uint32_t*)(As  + k0 + 8);
        uint32_t a3 = *(const uint32_t*)(As8 + k0 + 8);
#pragma unroll
        for (int nt = 0; nt < 4; nt++) {
            const __half* Bs = w_s + ((nh * 4 + nt) * 8 + g) * 136;
            uint32_t b0 = *(const uint32_t*)(Bs + k0);
            uint32_t b1 = *(const uint32_t*)(Bs + k0 + 8);
            asm volatile(
                "mma.sync.aligned.m16n8k16.row.col.f32.f16.f16.f32 "
                "{%0,%1,%2,%3}, {%4,%5,%6,%7}, {%8,%9}, {%0,%1,%2,%3};"
                : "+f"(c[nt][0]), "+f"(c[nt][1]), "+f"(c[nt][2]), "+f"(c[nt][3])
                : "r"(a0), "r"(a1), "r"(a2), "r"(a3), "r"(b0), "r"(b1));
        }
    }

    // epilogue: bias add, fp16 store of pre-BN h, BN stats
    int gn0 = base + row0;
    int gn8 = gn0 + 8;
    bool v0 = gn0 < NN, v8 = gn8 < NN;
#pragma unroll
    for (int nt = 0; nt < 4; nt++) {
        int col = (nh * 4 + nt) * 8 + 2 * iq;
        float b0v = __ldg(bias + col), b1v = __ldg(bias + col + 1);
        float h0 = c[nt][0] + b0v, h1 = c[nt][1] + b1v;
        float h2 = c[nt][2] + b0v, h3 = c[nt][3] + b1v;
        if (v0) *(__half2*)(g_hpre + (size_t)gn0 * HD + col) = __floats2half2_rn(h0, h1);
        if (v8) *(__half2*)(g_hpre + (size_t)gn8 * HD + col) = __floats2half2_rn(h2, h3);
        float ps0 = (v0 ? h0 : 0.f) + (v8 ? h2 : 0.f);
        float ps1 = (v0 ? h1 : 0.f) + (v8 ? h3 : 0.f);
        float qs0 = (v0 ? h0 * h0 : 0.f) + (v8 ? h2 * h2 : 0.f);
        float qs1 = (v0 ? h1 * h1 : 0.f) + (v8 ? h3 * h3 : 0.f);
#pragma unroll
        for (int o = 4; o < 32; o <<= 1) {
            ps0 += __shfl_xor_sync(0xffffffffu, ps0, o);
            ps1 += __shfl_xor_sync(0xffffffffu, ps1, o);
            qs0 += __shfl_xor_sync(0xffffffffu, qs0, o);
            qs1 += __shfl_xor_sync(0xffffffffu, qs1, o);
        }
        if (g == 0) {
            red_add(&g_bnsum[stat * HD + col],     ps0);
            red_add(&g_bnsum[stat * HD + col + 1], ps1);
            red_add(&g_bnsq[stat * HD + col],      qs0);
            red_add(&g_bnsq[stat * HD + col + 1],  qs1);
        }
    }
}

// ---------------- mean-pool over graphs (sorted batch -> run-flush) ----------------
__global__ void pool_kernel(const int* __restrict__ batch) {
    const __half2* __restrict__ h16 = (const __half2*)g_h16C;
    int warp = (blockIdx.x * blockDim.x + threadIdx.x) >> 5;
    const int nwarps = NN / 32;  // 3125
    if (warp >= nwarps) return;
    int lane = threadIdx.x & 31;
    int n0 = warp * 32, n1 = n0 + 32;
    int cur = __ldg(batch + n0);
    int runStart = n0;
    float a0 = 0.f, a1 = 0.f;
    for (int n = n0; n < n1; n++) {
        int b = __ldg(batch + n);
        if (b != cur) {
            red_add(&g_pool[cur * HD + 2 * lane], a0);
            red_add(&g_pool[cur * HD + 2 * lane + 1], a1);
            if (lane == 0) red_add(&g_cnt[cur], (float)(n - runStart));
            cur = b; runStart = n; a0 = 0.f; a1 = 0.f;
        }
        float2 f = __half22float2(__ldg(h16 + (size_t)n * 32 + lane));
        a0 += f.x; a1 += f.y;
    }
    red_add(&g_pool[cur * HD + 2 * lane], a0);
    red_add(&g_pool[cur * HD + 2 * lane + 1], a1);
    if (lane == 0) red_add(&g_cnt[cur], (float)(n1 - runStart));
}

// ---------------- MLP head ----------------
__global__ void head_kernel(const float* __restrict__ fc1w, const float* __restrict__ fc1b,
                            const float* __restrict__ fc2w, const float* __restrict__ fc2b,
                            float* __restrict__ out) {
    __shared__ float w1s[64 * 64];
    int tid = threadIdx.x;  // 128
    for (int i = tid; i < 64 * 64; i += 128) w1s[i] = fc1w[i];
    __syncthreads();
    if (tid < NG) {
        float ci = 1.0f / fmaxf(g_cnt[tid], 1.0f);
        float p[64];
#pragma unroll
        for (int f = 0; f < 64; f++) p[f] = g_pool[tid * HD + f] * ci;
        float hid[64];
#pragma unroll
        for (int j = 0; j < 64; j++) {
            float acc = fc1b[j];
#pragma unroll
            for (int f = 0; f < 64; f++) acc = fmaf(p[f], w1s[j * 64 + f], acc);
            hid[j] = fmaxf(acc, 0.f);
        }
#pragma unroll
        for (int u = 0; u < 2; u++) {
            float acc = fc2b[u];
#pragma unroll
            for (int j = 0; j < 64; j++) acc = fmaf(hid[j], __ldg(fc2w + u * 64 + j), acc);
            out[tid * 2 + u] = acc;
        }
    }
}

// ---------------- launch ----------------
extern "C" void kernel_launch(void* const* d_in, const int* in_sizes, int n_in,
                              void* d_out, int out_size) {
    const float* x    = (const float*)d_in[0];
    const int*   ei   = (const int*)d_in[1];
    const int*   src  = ei;
    const int*   dst  = ei + NE;
    const int*   bat  = (const int*)d_in[2];
    const float* w1l  = (const float*)d_in[3];
    const float* b1   = (const float*)d_in[4];
    const float* w1r  = (const float*)d_in[5];
    const float* g1   = (const float*)d_in[6];
    const float* be1  = (const float*)d_in[7];
    const float* w2l  = (const float*)d_in[8];
    const float* b2   = (const float*)d_in[9];
    const float* w2r  = (const float*)d_in[10];
    const float* g2   = (const float*)d_in[11];
    const float* be2  = (const float*)d_in[12];
    const float* w3l  = (const float*)d_in[13];
    const float* b3   = (const float*)d_in[14];
    const float* w3r  = (const float*)d_in[15];
    const float* g3   = (const float*)d_in[16];
    const float* be3  = (const float*)d_in[17];
    const float* fc1w = (const float*)d_in[18];
    const float* fc1b = (const float*)d_in[19];
    const float* fc2w = (const float*)d_in[20];
    const float* fc2b = (const float*)d_in[21];
    float* out = (float*)d_out;

    // CSR build (place_kernel stays launch #4 -> profiled)
    zero_small_kernel<<<(NN + 255) / 256, 256>>>();
    hist_kernel<<<(NE + 255) / 256, 256>>>(dst);
    scan_kernel<<<NBLK, SCAN_BLK>>>();
    place_kernel<<<(NE + 255) / 256, 256>>>(src, dst);

    // layer 1
    gather1_kernel<<<(NN * 32 + 255) / 256, 256>>>(x);
    node1_kernel<<<(NN + 255) / 256, 256>>>(x, w1l, b1, w1r);
    cvt_kernel<<<(NN * 8 + 255) / 256, 256>>>(0, g1, be1);

    // layer 2 (fused gather + transform)
    layer23_kernel<<<(NN + 63) / 64, 256>>>(0, w2l, b2, w2r);
    cvt_kernel<<<(NN * 8 + 255) / 256, 256>>>(1, g2, be2);

    // layer 3
    layer23_kernel<<<(NN + 63) / 64, 256>>>(1, w3l, b3, w3r);
    cvt_kernel<<<(NN * 8 + 255) / 256, 256>>>(2, g3, be3);

    // pool + head
    pool_kernel<<<(NN + 255) / 256, 256>>>(bat);
    head_kernel<<<1, 128>>>(fc1w, fc1b, fc2w, fc2b, out);
}